// round 5
// baseline (speedup 1.0000x reference)
#include <cuda_runtime.h>
#include <math.h>

#define B_     2
#define S_     2048
#define DM     1024
#define H_     16
#define DK     64
#define INNER_ 1024
#define NREL   4095   // relative positions -2047..2047

// ---------------- device scratch (no allocations allowed) ----------------
__device__ float g_q[B_ * H_ * S_ * DK];     // [B,H,S,DK]
__device__ float g_k[B_ * H_ * S_ * DK];
__device__ float g_v[B_ * H_ * S_ * DK];
__device__ float g_ctx[B_ * S_ * INNER_];    // [B,S,H*DK]
__device__ float g_bias[H_ * NREL];          // bias per head per (k-q)+2047

// ---------------- relative position bias table ----------------
// Faithful port of T5 _relative_position_bucket (bidirectional, 32 buckets,
// max_distance=128). fp32 log, truncating int cast, matching jax fp32 math.
__global__ void bias_kernel(const float* __restrict__ table) {
    int idx = blockIdx.x * blockDim.x + threadIdx.x;
    if (idx >= H_ * NREL) return;
    int h   = idx / NREL;
    int rel = (idx % NREL) - 2047;      // rel = k - q
    int rb  = (rel > 0) ? 16 : 0;       // num_buckets//2
    int r   = abs(rel);
    int v;
    if (r < 8) {                        // max_exact = 8
        v = r;
    } else {
        // 8 + int( log(r/8)/log(16) * 8 ), clamped to 15
        float t = logf((float)r * 0.125f) / 2.7725887f * 8.0f;
        v = 8 + (int)t;
        v = min(v, 15);
    }
    int bucket = rb + v;
    g_bias[idx] = table[bucket * H_ + h];
}

// ---------------- SGEMM 128x128x8, 8x8 per thread ----------------
// C[M=4096, N=1024] = A[4096,1024] @ W[1024,1024]
// mode 1/2/3: A = Aopt, write permuted [B,H,S,DK] into g_q/g_k/g_v
// mode 0:    A = g_ctx, write plain row-major into Copt (final output proj)
__global__ __launch_bounds__(256) void gemm128(const float* __restrict__ Aopt,
                                               const float* __restrict__ W,
                                               float* __restrict__ Copt,
                                               int mode) {
    __shared__ float As[8][128];
    __shared__ float Bs[8][128];

    const float* A = (mode == 0) ? g_ctx : Aopt;
    const int K = 1024, N = 1024;

    int tid = threadIdx.x;
    int tx = tid & 15, ty = tid >> 4;
    int bx = blockIdx.x, by = blockIdx.y;

    float acc[8][8];
#pragma unroll
    for (int i = 0; i < 8; i++)
#pragma unroll
        for (int j = 0; j < 8; j++) acc[i][j] = 0.0f;

    int ar = tid >> 1, ac = (tid & 1) * 4;          // A: 128 rows x 8 cols
    int brow = tid >> 5, bcol = (tid & 31) * 4;     // B: 8 rows x 128 cols
    const float* Aptr = A + (size_t)(by * 128 + ar) * K + ac;
    const float* Bptr = W + (size_t)brow * N + bx * 128 + bcol;

    for (int kt = 0; kt < K; kt += 8) {
        float4 av = *(const float4*)(Aptr + kt);
        float4 bv = *(const float4*)(Bptr + (size_t)kt * N);
        As[ac + 0][ar] = av.x;
        As[ac + 1][ar] = av.y;
        As[ac + 2][ar] = av.z;
        As[ac + 3][ar] = av.w;
        *(float4*)&Bs[brow][bcol] = bv;
        __syncthreads();

#pragma unroll
        for (int k = 0; k < 8; k++) {
            float4 a0 = *(float4*)&As[k][ty * 8];
            float4 a1 = *(float4*)&As[k][ty * 8 + 4];
            float4 b0 = *(float4*)&Bs[k][tx * 8];
            float4 b1 = *(float4*)&Bs[k][tx * 8 + 4];
            float ra[8] = {a0.x, a0.y, a0.z, a0.w, a1.x, a1.y, a1.z, a1.w};
            float rbv[8] = {b0.x, b0.y, b0.z, b0.w, b1.x, b1.y, b1.z, b1.w};
#pragma unroll
            for (int i = 0; i < 8; i++)
#pragma unroll
                for (int j = 0; j < 8; j++) acc[i][j] += ra[i] * rbv[j];
        }
        __syncthreads();
    }

    // epilogue
    if (mode == 0) {
#pragma unroll
        for (int i = 0; i < 8; i++) {
            int row = by * 128 + ty * 8 + i;
#pragma unroll
            for (int j = 0; j < 8; j++) {
                int col = bx * 128 + tx * 8 + j;
                Copt[(size_t)row * N + col] = acc[i][j];
            }
        }
    } else {
        float* dst = (mode == 1) ? g_q : (mode == 2) ? g_k : g_v;
#pragma unroll
        for (int i = 0; i < 8; i++) {
            int row = by * 128 + ty * 8 + i;
            int b = row >> 11, s = row & 2047;
#pragma unroll
            for (int j = 0; j < 8; j++) {
                int col = bx * 128 + tx * 8 + j;
                int h = col >> 6, d = col & 63;
                dst[(size_t)((b * H_ + h) * S_ + s) * DK + d] = acc[i][j];
            }
        }
    }
}

// ---------------- flash attention, fp32, 64x64 tiles ----------------
#define BR 64
#define BC 64
#define TP 65  // smem pitch (pad to dodge bank conflicts)

__global__ __launch_bounds__(256) void flash_kernel() {
    extern __shared__ float sm[];
    float* Qs = sm;                 // BR*TP
    float* Ks = Qs + BR * TP;       // BC*TP
    float* Vs = Ks + BC * TP;       // BC*TP
    float* Ps = Vs + BC * TP;       // BR*TP
    float* sB = Ps + BR * TP;       // 127 bias values for this k-block

    int qb = blockIdx.x, h = blockIdx.y, b = blockIdx.z;
    int tid = threadIdx.x;
    int tx = tid & 15, ty = tid >> 4;

    const float* Qg = g_q + ((size_t)(b * H_ + h) * S_ + qb * BR) * DK;
    const float* Kg = g_k + (size_t)(b * H_ + h) * S_ * DK;
    const float* Vg = g_v + (size_t)(b * H_ + h) * S_ * DK;

    for (int i = tid; i < BR * DK; i += 256) {
        int r = i >> 6, c = i & 63;
        Qs[r * TP + c] = Qg[r * DK + c];
    }

    float m_i[4], l_i[4], acc[4][4];
#pragma unroll
    for (int i = 0; i < 4; i++) {
        m_i[i] = -1e30f;
        l_i[i] = 0.0f;
#pragma unroll
        for (int j = 0; j < 4; j++) acc[i][j] = 0.0f;
    }

    for (int kb = 0; kb < S_ / BC; kb++) {
        for (int i = tid; i < BC * DK; i += 256) {
            int r = i >> 6, c = i & 63;
            Ks[r * TP + c] = Kg[(kb * BC + r) * DK + c];
            Vs[r * TP + c] = Vg[(kb * BC + r) * DK + c];
        }
        if (tid < 127)
            sB[tid] = g_bias[h * NREL + (kb * BC - qb * BR) - 63 + 2047 + tid];
        __syncthreads();

        // S = Q Kt (64x64), thread owns 4x4 at (ty*4+i, tx*4+j)
        float s[4][4];
#pragma unroll
        for (int i = 0; i < 4; i++)
#pragma unroll
            for (int j = 0; j < 4; j++) s[i][j] = 0.0f;

#pragma unroll 8
        for (int d = 0; d < DK; d++) {
            float qr[4], kr[4];
#pragma unroll
            for (int i = 0; i < 4; i++) qr[i] = Qs[(ty * 4 + i) * TP + d];
#pragma unroll
            for (int j = 0; j < 4; j++) kr[j] = Ks[(tx * 4 + j) * TP + d];
#pragma unroll
            for (int i = 0; i < 4; i++)
#pragma unroll
                for (int j = 0; j < 4; j++) s[i][j] += qr[i] * kr[j];
        }

        // + position bias (function of (k-q); constant along diagonals)
#pragma unroll
        for (int i = 0; i < 4; i++)
#pragma unroll
            for (int j = 0; j < 4; j++)
                s[i][j] += sB[(tx * 4 + j) - (ty * 4 + i) + 63];

        // online softmax per row (16 tx lanes own one row)
#pragma unroll
        for (int i = 0; i < 4; i++) {
            float rm = fmaxf(fmaxf(s[i][0], s[i][1]), fmaxf(s[i][2], s[i][3]));
#pragma unroll
            for (int off = 8; off > 0; off >>= 1)
                rm = fmaxf(rm, __shfl_xor_sync(0xffffffffu, rm, off));
            float mn = fmaxf(m_i[i], rm);
            float corr = __expf(m_i[i] - mn);
            float p[4], rs = 0.0f;
#pragma unroll
            for (int j = 0; j < 4; j++) {
                p[j] = __expf(s[i][j] - mn);
                rs += p[j];
            }
#pragma unroll
            for (int off = 8; off > 0; off >>= 1)
                rs += __shfl_xor_sync(0xffffffffu, rs, off);
            l_i[i] = l_i[i] * corr + rs;
            m_i[i] = mn;
#pragma unroll
            for (int j = 0; j < 4; j++) acc[i][j] *= corr;
#pragma unroll
            for (int j = 0; j < 4; j++)
                Ps[(ty * 4 + i) * TP + tx * 4 + j] = p[j];
        }
        __syncthreads();

        // O += P @ V  (thread owns O[ty*4+i][tx*4+j], j = head-dim col)
#pragma unroll 8
        for (int k = 0; k < BC; k++) {
            float pr[4], vr[4];
#pragma unroll
            for (int i = 0; i < 4; i++) pr[i] = Ps[(ty * 4 + i) * TP + k];
#pragma unroll
            for (int j = 0; j < 4; j++) vr[j] = Vs[k * TP + tx * 4 + j];
#pragma unroll
            for (int i = 0; i < 4; i++)
#pragma unroll
                for (int j = 0; j < 4; j++) acc[i][j] += pr[i] * vr[j];
        }
        __syncthreads();
    }

    // write ctx in [B,S,H*DK] so the output GEMM is plain row-major
#pragma unroll
    for (int i = 0; i < 4; i++) {
        int q = qb * BR + ty * 4 + i;
        float inv_l = 1.0f / l_i[i];
#pragma unroll
        for (int j = 0; j < 4; j++)
            g_ctx[((size_t)b * S_ + q) * INNER_ + h * DK + tx * 4 + j] =
                acc[i][j] * inv_l;
    }
}

// ---------------- launch ----------------
extern "C" void kernel_launch(void* const* d_in, const int* in_sizes, int n_in,
                              void* d_out, int out_size) {
    const float* X     = (const float*)d_in[0];
    const float* wq    = (const float*)d_in[1];
    const float* wk    = (const float*)d_in[2];
    const float* wv    = (const float*)d_in[3];
    const float* wo    = (const float*)d_in[4];
    const float* table = (const float*)d_in[5];
    float* out = (float*)d_out;

    // 1. relative-position bias table
    bias_kernel<<<(H_ * NREL + 255) / 256, 256>>>(table);

    // 2. Q/K/V projections (epilogue permutes into [B,H,S,DK])
    dim3 gg(INNER_ / 128, (B_ * S_) / 128);
    gemm128<<<gg, 256>>>(X, wq, nullptr, 1);
    gemm128<<<gg, 256>>>(X, wk, nullptr, 2);
    gemm128<<<gg, 256>>>(X, wv, nullptr, 3);

    // 3. flash attention
    int smem = (4 * BR * TP + 128) * (int)sizeof(float);
    cudaFuncSetAttribute(flash_kernel,
                         cudaFuncAttributeMaxDynamicSharedMemorySize, smem);
    dim3 ga(S_ / BR, H_, B_);
    flash_kernel<<<ga, 256, smem>>>();

    // 4. output projection
    dim3 go(DM / 128, (B_ * S_) / 128);
    gemm128<<<go, 256>>>(nullptr, wo, out, 0);
}

// round 9
// speedup vs baseline: 1.3693x; 1.3693x over previous
#include <cuda_runtime.h>
#include <math.h>

#define B_     2
#define S_     2048
#define DM     1024
#define H_     16
#define DK     64
#define INNER_ 1024
#define NREL   4095   // relative positions -2047..2047

// ---------------- device scratch ----------------
__device__ float g_q[B_ * H_ * S_ * DK];     // [B,H,S,DK]
__device__ float g_k[B_ * H_ * S_ * DK];
__device__ float g_v[B_ * H_ * S_ * DK];
__device__ float g_ctx[B_ * S_ * INNER_];    // [B,S,H*DK]
__device__ float g_bias[H_ * NREL];          // bias per head per (k-q)+2047

// ---------------- tf32 helpers ----------------
__device__ __forceinline__ unsigned f2tf(float x) {
    unsigned u;
    asm("cvt.rna.tf32.f32 %0, %1;" : "=r"(u) : "f"(x));
    return u;
}
// split x into hi (tf32) + lo (tf32 of exact residual)
__device__ __forceinline__ void split_tf32(float x, unsigned& hi, unsigned& lo) {
    hi = f2tf(x);
    lo = f2tf(x - __uint_as_float(hi));
}

__device__ __forceinline__ void mma_tf32(float* c, unsigned a0, unsigned a1,
                                         unsigned a2, unsigned a3,
                                         unsigned b0, unsigned b1) {
    asm volatile(
        "mma.sync.aligned.m16n8k8.row.col.f32.tf32.tf32.f32 "
        "{%0,%1,%2,%3}, {%4,%5,%6,%7}, {%8,%9}, {%0,%1,%2,%3};\n"
        : "+f"(c[0]), "+f"(c[1]), "+f"(c[2]), "+f"(c[3])
        : "r"(a0), "r"(a1), "r"(a2), "r"(a3), "r"(b0), "r"(b1));
}

// 3-term 3xTF32: aH*bH + aH*bL + aL*bH  (~2^-22 effective precision)
__device__ __forceinline__ void mma3(float* c, const unsigned* aH,
                                     const unsigned* aL, unsigned bH0,
                                     unsigned bH1, unsigned bL0, unsigned bL1) {
    mma_tf32(c, aH[0], aH[1], aH[2], aH[3], bH0, bH1);
    mma_tf32(c, aH[0], aH[1], aH[2], aH[3], bL0, bL1);
    mma_tf32(c, aL[0], aL[1], aL[2], aL[3], bH0, bH1);
}

// ---------------- relative position bias table ----------------
__global__ void bias_kernel(const float* __restrict__ table) {
    int idx = blockIdx.x * blockDim.x + threadIdx.x;
    if (idx >= H_ * NREL) return;
    int h   = idx / NREL;
    int rel = (idx % NREL) - 2047;      // rel = k - q
    int rb  = (rel > 0) ? 16 : 0;
    int r   = abs(rel);
    int v;
    if (r < 8) {
        v = r;
    } else {
        float t = logf((float)r * 0.125f) / 2.7725887f * 8.0f;
        v = 8 + (int)t;
        v = min(v, 15);
    }
    g_bias[idx] = table[(rb + v) * H_ + h];
}

// ---------------- 3xTF32 tensor-core GEMM 128x128x32 ----------------
// C[4096,1024] = A[4096,1024] @ W[1024,1024]
// mode 1/2/3: A=Aopt, permuted write to g_q/g_k/g_v ([B,H,S,DK])
// mode 0:     A=g_ctx, plain row-major write to Copt
#define APITCH 36
#define BPITCH 136
#define GEMM_SMEM ((2 * 128 * APITCH + 2 * 32 * BPITCH) * 4)

__global__ __launch_bounds__(256) void gemm_tf32(const float* __restrict__ Aopt,
                                                 const float* __restrict__ W,
                                                 float* __restrict__ Copt,
                                                 int mode) {
    extern __shared__ unsigned smg[];
    unsigned* AsH = smg;                       // [128][36]
    unsigned* AsL = AsH + 128 * APITCH;
    unsigned* BsH = AsL + 128 * APITCH;        // [32][136]
    unsigned* BsL = BsH + 32 * BPITCH;

    const float* A = (mode == 0) ? g_ctx : Aopt;
    const int K = 1024, N = 1024;

    int tid  = threadIdx.x;
    int warp = tid >> 5, lane = tid & 31;
    int g = lane >> 2, tig = lane & 3;
    int wm = (warp >> 2) * 64;       // warp M offset
    int wn = (warp & 3) * 32;        // warp N offset
    int bx = blockIdx.x, by = blockIdx.y;

    float acc[4][4][4];
#pragma unroll
    for (int mi = 0; mi < 4; mi++)
#pragma unroll
        for (int ni = 0; ni < 4; ni++)
#pragma unroll
            for (int c = 0; c < 4; c++) acc[mi][ni][c] = 0.0f;

    float4 aR[4], bR[4];

    // prefetch tile 0
#pragma unroll
    for (int i = 0; i < 4; i++) {
        int ch = tid + i * 256;
        int r = ch >> 3, c = (ch & 7) * 4;
        aR[i] = *(const float4*)(A + (size_t)(by * 128 + r) * K + c);
        int r2 = ch >> 5, c2 = (ch & 31) * 4;
        bR[i] = *(const float4*)(W + (size_t)r2 * N + bx * 128 + c2);
    }

    for (int kt = 0; kt < K / 32; kt++) {
        // store prefetched tile split into hi/lo tf32
#pragma unroll
        for (int i = 0; i < 4; i++) {
            int ch = tid + i * 256;
            int r = ch >> 3, c = (ch & 7) * 4;
            uint4 uh, ul;
            split_tf32(aR[i].x, uh.x, ul.x);
            split_tf32(aR[i].y, uh.y, ul.y);
            split_tf32(aR[i].z, uh.z, ul.z);
            split_tf32(aR[i].w, uh.w, ul.w);
            *(uint4*)&AsH[r * APITCH + c] = uh;
            *(uint4*)&AsL[r * APITCH + c] = ul;
            int r2 = ch >> 5, c2 = (ch & 31) * 4;
            uint4 vh, vl;
            split_tf32(bR[i].x, vh.x, vl.x);
            split_tf32(bR[i].y, vh.y, vl.y);
            split_tf32(bR[i].z, vh.z, vl.z);
            split_tf32(bR[i].w, vh.w, vl.w);
            *(uint4*)&BsH[r2 * BPITCH + c2] = vh;
            *(uint4*)&BsL[r2 * BPITCH + c2] = vl;
        }
        __syncthreads();

        // prefetch next tile
        if (kt + 1 < K / 32) {
            int k0 = (kt + 1) * 32;
#pragma unroll
            for (int i = 0; i < 4; i++) {
                int ch = tid + i * 256;
                int r = ch >> 3, c = (ch & 7) * 4;
                aR[i] = *(const float4*)(A + (size_t)(by * 128 + r) * K + k0 + c);
                int r2 = ch >> 5, c2 = (ch & 31) * 4;
                bR[i] = *(const float4*)(W + (size_t)(k0 + r2) * N + bx * 128 + c2);
            }
        }

        // compute
#pragma unroll
        for (int ks = 0; ks < 4; ks++) {
            int k = ks * 8;
            unsigned afH[4][4], afL[4][4], bfH[4][2], bfL[4][2];
#pragma unroll
            for (int mi = 0; mi < 4; mi++) {
                int r = wm + mi * 16 + g;
                afH[mi][0] = AsH[r * APITCH + k + tig];
                afH[mi][1] = AsH[(r + 8) * APITCH + k + tig];
                afH[mi][2] = AsH[r * APITCH + k + tig + 4];
                afH[mi][3] = AsH[(r + 8) * APITCH + k + tig + 4];
                afL[mi][0] = AsL[r * APITCH + k + tig];
                afL[mi][1] = AsL[(r + 8) * APITCH + k + tig];
                afL[mi][2] = AsL[r * APITCH + k + tig + 4];
                afL[mi][3] = AsL[(r + 8) * APITCH + k + tig + 4];
            }
#pragma unroll
            for (int ni = 0; ni < 4; ni++) {
                int c = wn + ni * 8 + g;
                bfH[ni][0] = BsH[(k + tig) * BPITCH + c];
                bfH[ni][1] = BsH[(k + tig + 4) * BPITCH + c];
                bfL[ni][0] = BsL[(k + tig) * BPITCH + c];
                bfL[ni][1] = BsL[(k + tig + 4) * BPITCH + c];
            }
#pragma unroll
            for (int mi = 0; mi < 4; mi++)
#pragma unroll
                for (int ni = 0; ni < 4; ni++)
                    mma3(acc[mi][ni], afH[mi], afL[mi], bfH[ni][0], bfH[ni][1],
                         bfL[ni][0], bfL[ni][1]);
        }
        __syncthreads();
    }

    // epilogue
    if (mode == 0) {
#pragma unroll
        for (int mi = 0; mi < 4; mi++)
#pragma unroll
            for (int ni = 0; ni < 4; ni++) {
                int r0 = by * 128 + wm + mi * 16 + g;
                int c0 = bx * 128 + wn + ni * 8 + tig * 2;
                *(float2*)(Copt + (size_t)r0 * N + c0) =
                    make_float2(acc[mi][ni][0], acc[mi][ni][1]);
                *(float2*)(Copt + (size_t)(r0 + 8) * N + c0) =
                    make_float2(acc[mi][ni][2], acc[mi][ni][3]);
            }
    } else {
        float* dst = (mode == 1) ? g_q : (mode == 2) ? g_k : g_v;
#pragma unroll
        for (int mi = 0; mi < 4; mi++)
#pragma unroll
            for (int ni = 0; ni < 4; ni++) {
                int r0 = by * 128 + wm + mi * 16 + g;
                int c0 = bx * 128 + wn + ni * 8 + tig * 2;
                int h = c0 >> 6, d = c0 & 63;
                {
                    int b = r0 >> 11, s = r0 & 2047;
                    *(float2*)(dst + (size_t)((b * H_ + h) * S_ + s) * DK + d) =
                        make_float2(acc[mi][ni][0], acc[mi][ni][1]);
                }
                {
                    int r1 = r0 + 8;
                    int b = r1 >> 11, s = r1 & 2047;
                    *(float2*)(dst + (size_t)((b * H_ + h) * S_ + s) * DK + d) =
                        make_float2(acc[mi][ni][2], acc[mi][ni][3]);
                }
            }
    }
}

// ---------------- 3xTF32 flash attention, 128x64 tiles, 8 warps ----------------
#define FP_Q 68
#define FP_K 68
#define FP_V 72
#define FP_P 68
#define FLASH_SMEM ((2 * 128 * FP_Q + 2 * 64 * FP_K + 2 * 64 * FP_V + \
                     2 * 128 * FP_P + 192) * 4)

__global__ __launch_bounds__(256) void flash_tf32() {
    extern __shared__ unsigned smu[];
    unsigned* QsH = smu;                    // [128][68]
    unsigned* QsL = QsH + 128 * FP_Q;
    unsigned* KsH = QsL + 128 * FP_Q;       // [64][68]
    unsigned* KsL = KsH + 64 * FP_K;
    unsigned* VsH = KsL + 64 * FP_K;        // [64][72]
    unsigned* VsL = VsH + 64 * FP_V;
    unsigned* PsH = VsL + 64 * FP_V;        // [128][68]
    unsigned* PsL = PsH + 128 * FP_P;
    float* sB = (float*)(PsL + 128 * FP_P); // 191 bias values

    int qb = blockIdx.x, h = blockIdx.y, b = blockIdx.z;
    int tid  = threadIdx.x;
    int warp = tid >> 5, lane = tid & 31;
    int g = lane >> 2, tig = lane & 3;

    const float* Qg = g_q + ((size_t)(b * H_ + h) * S_ + qb * 128) * DK;
    const float* Kg = g_k + (size_t)(b * H_ + h) * S_ * DK;
    const float* Vg = g_v + (size_t)(b * H_ + h) * S_ * DK;

    // load Q tile (128x64), split to tf32 hi/lo
#pragma unroll
    for (int i = 0; i < 8; i++) {
        int ch = tid + i * 256;
        int r = ch >> 4, c = (ch & 15) * 4;
        float4 v = *(const float4*)(Qg + (size_t)r * DK + c);
        uint4 uh, ul;
        split_tf32(v.x, uh.x, ul.x);
        split_tf32(v.y, uh.y, ul.y);
        split_tf32(v.z, uh.z, ul.z);
        split_tf32(v.w, uh.w, ul.w);
        *(uint4*)&QsH[r * FP_Q + c] = uh;
        *(uint4*)&QsL[r * FP_Q + c] = ul;
    }

    float oacc[8][4];
#pragma unroll
    for (int ni = 0; ni < 8; ni++)
#pragma unroll
        for (int c = 0; c < 4; c++) oacc[ni][c] = 0.0f;
    float m_i[2] = {-1e30f, -1e30f}, l_i[2] = {0.0f, 0.0f};

    for (int kb = 0; kb < S_ / 64; kb++) {
        // load K, V tiles (64x64)
#pragma unroll
        for (int i = 0; i < 4; i++) {
            int ch = tid + i * 256;
            int r = ch >> 4, c = (ch & 15) * 4;
            float4 kv = *(const float4*)(Kg + (size_t)(kb * 64 + r) * DK + c);
            uint4 uh, ul;
            split_tf32(kv.x, uh.x, ul.x);
            split_tf32(kv.y, uh.y, ul.y);
            split_tf32(kv.z, uh.z, ul.z);
            split_tf32(kv.w, uh.w, ul.w);
            *(uint4*)&KsH[r * FP_K + c] = uh;
            *(uint4*)&KsL[r * FP_K + c] = ul;
            float4 vv = *(const float4*)(Vg + (size_t)(kb * 64 + r) * DK + c);
            uint4 wh, wl;
            split_tf32(vv.x, wh.x, wl.x);
            split_tf32(vv.y, wh.y, wl.y);
            split_tf32(vv.z, wh.z, wl.z);
            split_tf32(vv.w, wh.w, wl.w);
            *(uint4*)&VsH[r * FP_V + c] = wh;
            *(uint4*)&VsL[r * FP_V + c] = wl;
        }
        // rel = (kb*64 + kc') - (qb*128 + qr'), kc' in [0,64), qr' in [0,128)
        if (tid < 191)
            sB[tid] = g_bias[h * NREL + (kb * 64 - qb * 128) - 127 + 2047 + tid];
        __syncthreads();

        // S = Q @ K^T  (warp: rows [16w,16w+16) x 64 cols)
        float sacc[8][4];
#pragma unroll
        for (int ni = 0; ni < 8; ni++)
#pragma unroll
            for (int c = 0; c < 4; c++) sacc[ni][c] = 0.0f;

#pragma unroll
        for (int ks = 0; ks < 8; ks++) {
            int k = ks * 8;
            int rq = warp * 16 + g;
            unsigned aH[4], aL[4];
            aH[0] = QsH[rq * FP_Q + k + tig];
            aH[1] = QsH[(rq + 8) * FP_Q + k + tig];
            aH[2] = QsH[rq * FP_Q + k + tig + 4];
            aH[3] = QsH[(rq + 8) * FP_Q + k + tig + 4];
            aL[0] = QsL[rq * FP_Q + k + tig];
            aL[1] = QsL[(rq + 8) * FP_Q + k + tig];
            aL[2] = QsL[rq * FP_Q + k + tig + 4];
            aL[3] = QsL[(rq + 8) * FP_Q + k + tig + 4];
#pragma unroll
            for (int ni = 0; ni < 8; ni++) {
                int rk = ni * 8 + g;
                unsigned bH0 = KsH[rk * FP_K + k + tig];
                unsigned bH1 = KsH[rk * FP_K + k + tig + 4];
                unsigned bL0 = KsL[rk * FP_K + k + tig];
                unsigned bL1 = KsL[rk * FP_K + k + tig + 4];
                mma3(sacc[ni], aH, aL, bH0, bH1, bL0, bL1);
            }
        }

        // bias + online softmax (per half-row rh: rows g, g+8 of warp tile)
#pragma unroll
        for (int rh = 0; rh < 2; rh++) {
            int qr = warp * 16 + g + 8 * rh;     // local q row 0..127
            float rm = -1e30f;
#pragma unroll
            for (int ni = 0; ni < 8; ni++) {
                int kc = ni * 8 + tig * 2;
                sacc[ni][2 * rh]     += sB[kc - qr + 127];
                sacc[ni][2 * rh + 1] += sB[kc + 1 - qr + 127];
                rm = fmaxf(rm, fmaxf(sacc[ni][2 * rh], sacc[ni][2 * rh + 1]));
            }
            rm = fmaxf(rm, __shfl_xor_sync(0xffffffffu, rm, 1));
            rm = fmaxf(rm, __shfl_xor_sync(0xffffffffu, rm, 2));
            float mn   = fmaxf(m_i[rh], rm);
            float corr = __expf(m_i[rh] - mn);
            float rs = 0.0f;
#pragma unroll
            for (int ni = 0; ni < 8; ni++) {
                float p0 = __expf(sacc[ni][2 * rh] - mn);
                float p1 = __expf(sacc[ni][2 * rh + 1] - mn);
                rs += p0 + p1;
                uint2 ph, pl;
                split_tf32(p0, ph.x, pl.x);
                split_tf32(p1, ph.y, pl.y);
                *(uint2*)&PsH[qr * FP_P + ni * 8 + tig * 2] = ph;
                *(uint2*)&PsL[qr * FP_P + ni * 8 + tig * 2] = pl;
                oacc[ni][2 * rh]     *= corr;
                oacc[ni][2 * rh + 1] *= corr;
            }
            rs += __shfl_xor_sync(0xffffffffu, rs, 1);
            rs += __shfl_xor_sync(0xffffffffu, rs, 2);
            l_i[rh] = l_i[rh] * corr + rs;
            m_i[rh] = mn;
        }
        __syncwarp();   // P rows are warp-private

        // O += P @ V
#pragma unroll
        for (int ks = 0; ks < 8; ks++) {
            int k = ks * 8;
            int pr = warp * 16 + g;
            unsigned aH[4], aL[4];
            aH[0] = PsH[pr * FP_P + k + tig];
            aH[1] = PsH[(pr + 8) * FP_P + k + tig];
            aH[2] = PsH[pr * FP_P + k + tig + 4];
            aH[3] = PsH[(pr + 8) * FP_P + k + tig + 4];
            aL[0] = PsL[pr * FP_P + k + tig];
            aL[1] = PsL[(pr + 8) * FP_P + k + tig];
            aL[2] = PsL[pr * FP_P + k + tig + 4];
            aL[3] = PsL[(pr + 8) * FP_P + k + tig + 4];
#pragma unroll
            for (int ni = 0; ni < 8; ni++) {
                unsigned bH0 = VsH[(k + tig) * FP_V + ni * 8 + g];
                unsigned bH1 = VsH[(k + tig + 4) * FP_V + ni * 8 + g];
                unsigned bL0 = VsL[(k + tig) * FP_V + ni * 8 + g];
                unsigned bL1 = VsL[(k + tig + 4) * FP_V + ni * 8 + g];
                mma3(oacc[ni], aH, aL, bH0, bH1, bL0, bL1);
            }
        }
        __syncthreads();
    }

    // normalize + write ctx in [B,S,H*DK]
    float inv0 = 1.0f / l_i[0], inv1 = 1.0f / l_i[1];
#pragma unroll
    for (int ni = 0; ni < 8; ni++) {
        int q0 = qb * 128 + warp * 16 + g;
        int d0 = ni * 8 + tig * 2;
        *(float2*)(g_ctx + ((size_t)b * S_ + q0) * INNER_ + h * DK + d0) =
            make_float2(oacc[ni][0] * inv0, oacc[ni][1] * inv0);
        *(float2*)(g_ctx + ((size_t)b * S_ + q0 + 8) * INNER_ + h * DK + d0) =
            make_float2(oacc[ni][2] * inv1, oacc[ni][3] * inv1);
    }
}

// ---------------- launch ----------------
extern "C" void kernel_launch(void* const* d_in, const int* in_sizes, int n_in,
                              void* d_out, int out_size) {
    const float* X     = (const float*)d_in[0];
    const float* wq    = (const float*)d_in[1];
    const float* wk    = (const float*)d_in[2];
    const float* wv    = (const float*)d_in[3];
    const float* wo    = (const float*)d_in[4];
    const float* table = (const float*)d_in[5];
    float* out = (float*)d_out;

    cudaFuncSetAttribute(gemm_tf32,
                         cudaFuncAttributeMaxDynamicSharedMemorySize, GEMM_SMEM);
    cudaFuncSetAttribute(flash_tf32,
                         cudaFuncAttributeMaxDynamicSharedMemorySize, FLASH_SMEM);

    // 1. relative-position bias table
    bias_kernel<<<(H_ * NREL + 255) / 256, 256>>>(table);

    // 2. Q/K/V projections
    dim3 gg(INNER_ / 128, (B_ * S_) / 128);
    gemm_tf32<<<gg, 256, GEMM_SMEM>>>(X, wq, nullptr, 1);
    gemm_tf32<<<gg, 256, GEMM_SMEM>>>(X, wk, nullptr, 2);
    gemm_tf32<<<gg, 256, GEMM_SMEM>>>(X, wv, nullptr, 3);

    // 3. flash attention
    dim3 ga(S_ / 128, H_, B_);
    flash_tf32<<<ga, 256, FLASH_SMEM>>>();

    // 4. output projection
    dim3 go(DM / 128, (B_ * S_) / 128);
    gemm_tf32<<<go, 256, GEMM_SMEM>>>(nullptr, wo, out, 0);
}

// round 10
// speedup vs baseline: 2.6634x; 1.9451x over previous
#include <cuda_runtime.h>
#include <cuda_bf16.h>
#include <math.h>

#define B_     2
#define S_     2048
#define DM     1024
#define H_     16
#define DK     64
#define INNER_ 1024
#define NREL   4095   // relative positions -2047..2047

// ---------------- device scratch ----------------
__device__ float g_q[B_ * H_ * S_ * DK];     // [B,H,S,DK]
__device__ float g_k[B_ * H_ * S_ * DK];
__device__ float g_v[B_ * H_ * S_ * DK];
__device__ float g_ctx[B_ * S_ * INNER_];    // [B,S,H*DK]
__device__ float g_bias[H_ * NREL];          // bias per head per (k-q)+2047

// ---------------- bf16 helpers ----------------
__device__ __forceinline__ unsigned packbf(float x0, float x1) {
    __nv_bfloat162 t = __floats2bfloat162_rn(x0, x1);   // low = x0 (smaller k)
    return *reinterpret_cast<unsigned*>(&t);
}
// split pair (x0,x1) into packed hi (bf16) and packed lo (bf16 of residual)
__device__ __forceinline__ void split2(float x0, float x1,
                                       unsigned& h, unsigned& l) {
    float h0 = __bfloat162float(__float2bfloat16_rn(x0));
    float h1 = __bfloat162float(__float2bfloat16_rn(x1));
    h = packbf(h0, h1);
    l = packbf(x0 - h0, x1 - h1);
}

__device__ __forceinline__ void mma_bf16(float* c, unsigned a0, unsigned a1,
                                         unsigned a2, unsigned a3,
                                         unsigned b0, unsigned b1) {
    asm volatile(
        "mma.sync.aligned.m16n8k16.row.col.f32.bf16.bf16.f32 "
        "{%0,%1,%2,%3}, {%4,%5,%6,%7}, {%8,%9}, {%0,%1,%2,%3};\n"
        : "+f"(c[0]), "+f"(c[1]), "+f"(c[2]), "+f"(c[3])
        : "r"(a0), "r"(a1), "r"(a2), "r"(a3), "r"(b0), "r"(b1));
}

// 3-term: aH*bH + aH*bL + aL*bH  (~2^-17 effective product precision)
__device__ __forceinline__ void mma3(float* c, const unsigned* aH,
                                     const unsigned* aL, unsigned bH0,
                                     unsigned bH1, unsigned bL0, unsigned bL1) {
    mma_bf16(c, aH[0], aH[1], aH[2], aH[3], bH0, bH1);
    mma_bf16(c, aH[0], aH[1], aH[2], aH[3], bL0, bL1);
    mma_bf16(c, aL[0], aL[1], aL[2], aL[3], bH0, bH1);
}

// ---------------- relative position bias table ----------------
__global__ void bias_kernel(const float* __restrict__ table) {
    int idx = blockIdx.x * blockDim.x + threadIdx.x;
    if (idx >= H_ * NREL) return;
    int h   = idx / NREL;
    int rel = (idx % NREL) - 2047;      // rel = k - q
    int rb  = (rel > 0) ? 16 : 0;
    int r   = abs(rel);
    int v;
    if (r < 8) {
        v = r;
    } else {
        float t = logf((float)r * 0.125f) / 2.7725887f * 8.0f;
        v = 8 + (int)t;
        v = min(v, 15);
    }
    g_bias[idx] = table[(rb + v) * H_ + h];
}

// ---------------- 3xBF16 tensor-core GEMM 128x128x32 ----------------
// mode 1: A=X, W selected by blockIdx.z (wq/wk/wv), permuted write to g_q/g_k/g_v
// mode 0: A=g_ctx, W=W0, plain row-major write to Copt
#define APITCH 20     // k-pair pitch for A tiles (16 pairs + pad)
#define BPITCH 136    // col pitch for B tiles
#define GEMM_SMEM ((2 * 128 * APITCH + 2 * 16 * BPITCH) * 4)

__global__ __launch_bounds__(256) void gemm_bf16x3(
    const float* __restrict__ X, const float* __restrict__ W0,
    const float* __restrict__ W1, const float* __restrict__ W2,
    float* __restrict__ Copt, int mode) {
    extern __shared__ unsigned smg[];
    unsigned* AsH = smg;                       // [128][20] packed k-pairs
    unsigned* AsL = AsH + 128 * APITCH;
    unsigned* BsH = AsL + 128 * APITCH;        // [16 pairs][136] cols
    unsigned* BsL = BsH + 16 * BPITCH;

    const int K = 1024, N = 1024;
    int z = blockIdx.z;
    const float* A = (mode == 0) ? g_ctx : X;
    const float* W = (mode == 0) ? W0 : (z == 0 ? W0 : (z == 1 ? W1 : W2));

    int tid  = threadIdx.x;
    int warp = tid >> 5, lane = tid & 31;
    int g = lane >> 2, tig = lane & 3;
    int wm = (warp >> 2) * 64;
    int wn = (warp & 3) * 32;
    int bx = blockIdx.x, by = blockIdx.y;

    float acc[4][4][4];
#pragma unroll
    for (int mi = 0; mi < 4; mi++)
#pragma unroll
        for (int ni = 0; ni < 4; ni++)
#pragma unroll
            for (int c = 0; c < 4; c++) acc[mi][ni][c] = 0.0f;

    float4 aR[4], bR[4];

    // prefetch tile 0
#pragma unroll
    for (int i = 0; i < 4; i++) {
        int ch = tid + i * 256;
        int r = ch >> 3, cq = ch & 7;
        aR[i] = *(const float4*)(A + (size_t)(by * 128 + r) * K + cq * 4);
    }
#pragma unroll
    for (int i = 0; i < 2; i++) {
        int u = tid + i * 256;
        int p = u >> 5, cq = u & 31;
        bR[2 * i]     = *(const float4*)(W + (size_t)(2 * p) * N + bx * 128 + cq * 4);
        bR[2 * i + 1] = *(const float4*)(W + (size_t)(2 * p + 1) * N + bx * 128 + cq * 4);
    }

    for (int kt = 0; kt < K / 32; kt++) {
        // store prefetched tile, split hi/lo bf16
#pragma unroll
        for (int i = 0; i < 4; i++) {
            int ch = tid + i * 256;
            int r = ch >> 3, cq = ch & 7;
            uint2 h, l;
            split2(aR[i].x, aR[i].y, h.x, l.x);
            split2(aR[i].z, aR[i].w, h.y, l.y);
            *(uint2*)&AsH[r * APITCH + cq * 2] = h;
            *(uint2*)&AsL[r * APITCH + cq * 2] = l;
        }
#pragma unroll
        for (int i = 0; i < 2; i++) {
            int u = tid + i * 256;
            int p = u >> 5, cq = u & 31;
            float4 ra = bR[2 * i], rb = bR[2 * i + 1];   // rows 2p, 2p+1
            uint4 h, l;
            split2(ra.x, rb.x, h.x, l.x);
            split2(ra.y, rb.y, h.y, l.y);
            split2(ra.z, rb.z, h.z, l.z);
            split2(ra.w, rb.w, h.w, l.w);
            *(uint4*)&BsH[p * BPITCH + cq * 4] = h;
            *(uint4*)&BsL[p * BPITCH + cq * 4] = l;
        }
        __syncthreads();

        // prefetch next tile
        if (kt + 1 < K / 32) {
            int k0 = (kt + 1) * 32;
#pragma unroll
            for (int i = 0; i < 4; i++) {
                int ch = tid + i * 256;
                int r = ch >> 3, cq = ch & 7;
                aR[i] = *(const float4*)(A + (size_t)(by * 128 + r) * K + k0 + cq * 4);
            }
#pragma unroll
            for (int i = 0; i < 2; i++) {
                int u = tid + i * 256;
                int p = u >> 5, cq = u & 31;
                bR[2 * i]     = *(const float4*)(W + (size_t)(k0 + 2 * p) * N + bx * 128 + cq * 4);
                bR[2 * i + 1] = *(const float4*)(W + (size_t)(k0 + 2 * p + 1) * N + bx * 128 + cq * 4);
            }
        }

        // compute: 2 k16 steps per 32-k tile
#pragma unroll
        for (int ks = 0; ks < 2; ks++) {
            int kp = ks * 8;    // pair base
            unsigned afH[4][4], afL[4][4], bfH[4][2], bfL[4][2];
#pragma unroll
            for (int mi = 0; mi < 4; mi++) {
                int r = wm + mi * 16 + g;
                afH[mi][0] = AsH[r * APITCH + kp + tig];
                afH[mi][1] = AsH[(r + 8) * APITCH + kp + tig];
                afH[mi][2] = AsH[r * APITCH + kp + tig + 4];
                afH[mi][3] = AsH[(r + 8) * APITCH + kp + tig + 4];
                afL[mi][0] = AsL[r * APITCH + kp + tig];
                afL[mi][1] = AsL[(r + 8) * APITCH + kp + tig];
                afL[mi][2] = AsL[r * APITCH + kp + tig + 4];
                afL[mi][3] = AsL[(r + 8) * APITCH + kp + tig + 4];
            }
#pragma unroll
            for (int ni = 0; ni < 4; ni++) {
                int c = wn + ni * 8 + g;
                bfH[ni][0] = BsH[(kp + tig) * BPITCH + c];
                bfH[ni][1] = BsH[(kp + tig + 4) * BPITCH + c];
                bfL[ni][0] = BsL[(kp + tig) * BPITCH + c];
                bfL[ni][1] = BsL[(kp + tig + 4) * BPITCH + c];
            }
#pragma unroll
            for (int mi = 0; mi < 4; mi++)
#pragma unroll
                for (int ni = 0; ni < 4; ni++)
                    mma3(acc[mi][ni], afH[mi], afL[mi], bfH[ni][0], bfH[ni][1],
                         bfL[ni][0], bfL[ni][1]);
        }
        __syncthreads();
    }

    // epilogue
    if (mode == 0) {
#pragma unroll
        for (int mi = 0; mi < 4; mi++)
#pragma unroll
            for (int ni = 0; ni < 4; ni++) {
                int r0 = by * 128 + wm + mi * 16 + g;
                int c0 = bx * 128 + wn + ni * 8 + tig * 2;
                *(float2*)(Copt + (size_t)r0 * N + c0) =
                    make_float2(acc[mi][ni][0], acc[mi][ni][1]);
                *(float2*)(Copt + (size_t)(r0 + 8) * N + c0) =
                    make_float2(acc[mi][ni][2], acc[mi][ni][3]);
            }
    } else {
        float* dst = (z == 0) ? g_q : (z == 1) ? g_k : g_v;
#pragma unroll
        for (int mi = 0; mi < 4; mi++)
#pragma unroll
            for (int ni = 0; ni < 4; ni++) {
                int r0 = by * 128 + wm + mi * 16 + g;
                int c0 = bx * 128 + wn + ni * 8 + tig * 2;
                int h = c0 >> 6, d = c0 & 63;
                {
                    int b = r0 >> 11, s = r0 & 2047;
                    *(float2*)(dst + (size_t)((b * H_ + h) * S_ + s) * DK + d) =
                        make_float2(acc[mi][ni][0], acc[mi][ni][1]);
                }
                {
                    int r1 = r0 + 8;
                    int b = r1 >> 11, s = r1 & 2047;
                    *(float2*)(dst + (size_t)((b * H_ + h) * S_ + s) * DK + d) =
                        make_float2(acc[mi][ni][2], acc[mi][ni][3]);
                }
            }
    }
}

// ---------------- 3xBF16 flash attention, 128x64 tiles, 8 warps ----------------
#define QP 36   // 32 k-pairs + pad
#define KP 36
#define VP 72   // 64 cols + pad (pair-rows)
#define PP 36
#define FLASH_SMEM ((2 * 128 * QP + 2 * 64 * KP + 2 * 32 * VP + \
                     2 * 128 * PP + 192) * 4)

__global__ __launch_bounds__(256) void flash_bf16x3() {
    extern __shared__ unsigned smu[];
    unsigned* QsH = smu;                    // [128 rows][36] packed d-pairs
    unsigned* QsL = QsH + 128 * QP;
    unsigned* KsH = QsL + 128 * QP;         // [64 rows][36]
    unsigned* KsL = KsH + 64 * KP;
    unsigned* VsH = KsL + 64 * KP;          // [32 k-pairs][72] cols
    unsigned* VsL = VsH + 32 * VP;
    unsigned* PsH = VsL + 32 * VP;          // [128 rows][36] packed k-pairs
    unsigned* PsL = PsH + 128 * PP;
    float* sB = (float*)(PsL + 128 * PP);   // 191 bias values

    int qb = blockIdx.x, h = blockIdx.y, b = blockIdx.z;
    int tid  = threadIdx.x;
    int warp = tid >> 5, lane = tid & 31;
    int g = lane >> 2, tig = lane & 3;

    const float* Qg = g_q + ((size_t)(b * H_ + h) * S_ + qb * 128) * DK;
    const float* Kg = g_k + (size_t)(b * H_ + h) * S_ * DK;
    const float* Vg = g_v + (size_t)(b * H_ + h) * S_ * DK;

    // load Q tile (128x64), split hi/lo, pack d-pairs
#pragma unroll
    for (int i = 0; i < 8; i++) {
        int ch = tid + i * 256;
        int r = ch >> 4, cq = ch & 15;
        float4 v = *(const float4*)(Qg + (size_t)r * DK + cq * 4);
        uint2 hh, ll;
        split2(v.x, v.y, hh.x, ll.x);
        split2(v.z, v.w, hh.y, ll.y);
        *(uint2*)&QsH[r * QP + cq * 2] = hh;
        *(uint2*)&QsL[r * QP + cq * 2] = ll;
    }

    float oacc[8][4];
#pragma unroll
    for (int ni = 0; ni < 8; ni++)
#pragma unroll
        for (int c = 0; c < 4; c++) oacc[ni][c] = 0.0f;
    float m_i[2] = {-1e30f, -1e30f}, l_i[2] = {0.0f, 0.0f};

    for (int kb = 0; kb < S_ / 64; kb++) {
        // K tile (64x64): row-major, d-pairs packed
#pragma unroll
        for (int i = 0; i < 4; i++) {
            int ch = tid + i * 256;
            int r = ch >> 4, cq = ch & 15;
            float4 kv = *(const float4*)(Kg + (size_t)(kb * 64 + r) * DK + cq * 4);
            uint2 hh, ll;
            split2(kv.x, kv.y, hh.x, ll.x);
            split2(kv.z, kv.w, hh.y, ll.y);
            *(uint2*)&KsH[r * KP + cq * 2] = hh;
            *(uint2*)&KsL[r * KP + cq * 2] = ll;
        }
        // V tile (64x64): k-pairs packed (rows 2p, 2p+1 interleaved per word)
#pragma unroll
        for (int i = 0; i < 2; i++) {
            int u = tid + i * 256;
            int p = u >> 4, cq = u & 15;
            float4 va = *(const float4*)(Vg + (size_t)(kb * 64 + 2 * p) * DK + cq * 4);
            float4 vb = *(const float4*)(Vg + (size_t)(kb * 64 + 2 * p + 1) * DK + cq * 4);
            uint4 hh, ll;
            split2(va.x, vb.x, hh.x, ll.x);
            split2(va.y, vb.y, hh.y, ll.y);
            split2(va.z, vb.z, hh.z, ll.z);
            split2(va.w, vb.w, hh.w, ll.w);
            *(uint4*)&VsH[p * VP + cq * 4] = hh;
            *(uint4*)&VsL[p * VP + cq * 4] = ll;
        }
        if (tid < 191)
            sB[tid] = g_bias[h * NREL + (kb * 64 - qb * 128) - 127 + 2047 + tid];
        __syncthreads();

        // S = Q @ K^T  (warp: rows [16w,16w+16) x 64 cols), 4 k16 steps over d
        float sacc[8][4];
#pragma unroll
        for (int ni = 0; ni < 8; ni++)
#pragma unroll
            for (int c = 0; c < 4; c++) sacc[ni][c] = 0.0f;

#pragma unroll
        for (int ks = 0; ks < 4; ks++) {
            int kp = ks * 8;
            int rq = warp * 16 + g;
            unsigned aH[4], aL[4];
            aH[0] = QsH[rq * QP + kp + tig];
            aH[1] = QsH[(rq + 8) * QP + kp + tig];
            aH[2] = QsH[rq * QP + kp + tig + 4];
            aH[3] = QsH[(rq + 8) * QP + kp + tig + 4];
            aL[0] = QsL[rq * QP + kp + tig];
            aL[1] = QsL[(rq + 8) * QP + kp + tig];
            aL[2] = QsL[rq * QP + kp + tig + 4];
            aL[3] = QsL[(rq + 8) * QP + kp + tig + 4];
#pragma unroll
            for (int ni = 0; ni < 8; ni++) {
                int rk = ni * 8 + g;
                unsigned bH0 = KsH[rk * KP + kp + tig];
                unsigned bH1 = KsH[rk * KP + kp + tig + 4];
                unsigned bL0 = KsL[rk * KP + kp + tig];
                unsigned bL1 = KsL[rk * KP + kp + tig + 4];
                mma3(sacc[ni], aH, aL, bH0, bH1, bL0, bL1);
            }
        }

        // bias + online softmax (per half-row rh: rows g, g+8 of warp tile)
#pragma unroll
        for (int rh = 0; rh < 2; rh++) {
            int qr = warp * 16 + g + 8 * rh;
            float rm = -1e30f;
#pragma unroll
            for (int ni = 0; ni < 8; ni++) {
                int kc = ni * 8 + tig * 2;
                sacc[ni][2 * rh]     += sB[kc - qr + 127];
                sacc[ni][2 * rh + 1] += sB[kc + 1 - qr + 127];
                rm = fmaxf(rm, fmaxf(sacc[ni][2 * rh], sacc[ni][2 * rh + 1]));
            }
            rm = fmaxf(rm, __shfl_xor_sync(0xffffffffu, rm, 1));
            rm = fmaxf(rm, __shfl_xor_sync(0xffffffffu, rm, 2));
            float mn   = fmaxf(m_i[rh], rm);
            float corr = __expf(m_i[rh] - mn);
            float rs = 0.0f;
#pragma unroll
            for (int ni = 0; ni < 8; ni++) {
                float p0 = __expf(sacc[ni][2 * rh] - mn);
                float p1 = __expf(sacc[ni][2 * rh + 1] - mn);
                rs += p0 + p1;
                unsigned ph, pl;
                split2(p0, p1, ph, pl);
                PsH[qr * PP + ni * 4 + tig] = ph;
                PsL[qr * PP + ni * 4 + tig] = pl;
                oacc[ni][2 * rh]     *= corr;
                oacc[ni][2 * rh + 1] *= corr;
            }
            rs += __shfl_xor_sync(0xffffffffu, rs, 1);
            rs += __shfl_xor_sync(0xffffffffu, rs, 2);
            l_i[rh] = l_i[rh] * corr + rs;
            m_i[rh] = mn;
        }
        __syncwarp();   // P rows are warp-private

        // O += P @ V  (4 k16 steps over the 64 kv positions)
#pragma unroll
        for (int ks = 0; ks < 4; ks++) {
            int kp = ks * 8;
            int pr = warp * 16 + g;
            unsigned aH[4], aL[4];
            aH[0] = PsH[pr * PP + kp + tig];
            aH[1] = PsH[(pr + 8) * PP + kp + tig];
            aH[2] = PsH[pr * PP + kp + tig + 4];
            aH[3] = PsH[(pr + 8) * PP + kp + tig + 4];
            aL[0] = PsL[pr * PP + kp + tig];
            aL[1] = PsL[(pr + 8) * PP + kp + tig];
            aL[2] = PsL[pr * PP + kp + tig + 4];
            aL[3] = PsL[(pr + 8) * PP + kp + tig + 4];
#pragma unroll
            for (int ni = 0; ni < 8; ni++) {
                int d = ni * 8 + g;
                unsigned bH0 = VsH[(kp + tig) * VP + d];
                unsigned bH1 = VsH[(kp + tig + 4) * VP + d];
                unsigned bL0 = VsL[(kp + tig) * VP + d];
                unsigned bL1 = VsL[(kp + tig + 4) * VP + d];
                mma3(oacc[ni], aH, aL, bH0, bH1, bL0, bL1);
            }
        }
        __syncthreads();
    }

    // normalize + write ctx in [B,S,H*DK]
    float inv0 = 1.0f / l_i[0], inv1 = 1.0f / l_i[1];
#pragma unroll
    for (int ni = 0; ni < 8; ni++) {
        int q0 = qb * 128 + warp * 16 + g;
        int d0 = ni * 8 + tig * 2;
        *(float2*)(g_ctx + ((size_t)b * S_ + q0) * INNER_ + h * DK + d0) =
            make_float2(oacc[ni][0] * inv0, oacc[ni][1] * inv0);
        *(float2*)(g_ctx + ((size_t)b * S_ + q0 + 8) * INNER_ + h * DK + d0) =
            make_float2(oacc[ni][2] * inv1, oacc[ni][3] * inv1);
    }
}

// ---------------- launch ----------------
extern "C" void kernel_launch(void* const* d_in, const int* in_sizes, int n_in,
                              void* d_out, int out_size) {
    const float* X     = (const float*)d_in[0];
    const float* wq    = (const float*)d_in[1];
    const float* wk    = (const float*)d_in[2];
    const float* wv    = (const float*)d_in[3];
    const float* wo    = (const float*)d_in[4];
    const float* table = (const float*)d_in[5];
    float* out = (float*)d_out;

    cudaFuncSetAttribute(gemm_bf16x3,
                         cudaFuncAttributeMaxDynamicSharedMemorySize, GEMM_SMEM);
    cudaFuncSetAttribute(flash_bf16x3,
                         cudaFuncAttributeMaxDynamicSharedMemorySize, FLASH_SMEM);

    // 1. relative-position bias table
    bias_kernel<<<(H_ * NREL + 255) / 256, 256>>>(table);

    // 2. fused Q/K/V projections (grid.z selects weight + destination)
    dim3 gq(INNER_ / 128, (B_ * S_) / 128, 3);
    gemm_bf16x3<<<gq, 256, GEMM_SMEM>>>(X, wq, wk, wv, nullptr, 1);

    // 3. flash attention
    dim3 ga(S_ / 128, H_, B_);
    flash_bf16x3<<<ga, 256, FLASH_SMEM>>>();

    // 4. output projection
    dim3 go(DM / 128, (B_ * S_) / 128, 1);
    gemm_bf16x3<<<go, 256, GEMM_SMEM>>>(nullptr, wo, nullptr, nullptr, out, 0);
}